// round 1
// baseline (speedup 1.0000x reference)
#include <cuda_runtime.h>
#include <cuda_bf16.h>

// ---------------------------------------------------------------------------
// GAT 2-layer forward.  Strategy:
//   1. counting-sort edges (incl. self loops) by dst -> CSR
//   2. GEMM1: h1 = x @ W1                       [20000 x 256]
//   3. att1:  a_s1/a_d1 per (node, head)
//   4. agg1:  per-dst-node block: single-pass softmax-weighted aggregation
//             (division by denom deferred to the end), +b1, ELU -> hE
//   5. GEMM2: h2 = hE @ W2 (+ fused a_s2/a_d2)  [20000 x 16]
//   6. agg2:  per-dst-node warp: same single-pass trick, +b2 -> out
// ---------------------------------------------------------------------------

#define NMAX 20000
#define EMAX 320000
#define ETMAX (NMAX + EMAX)

__device__ int   g_count[NMAX + 1];
__device__ int   g_off[NMAX + 1];
__device__ int   g_cursor[NMAX];
__device__ int   g_srcs[ETMAX];
__device__ float g_ews[ETMAX];

__device__ float g_h1[(size_t)NMAX * 256];
__device__ float g_hE[(size_t)NMAX * 256];
__device__ float g_as1[NMAX * 8];
__device__ float g_ad1[NMAX * 8];
__device__ float g_h2[NMAX * 16];
__device__ float g_as2[NMAX];
__device__ float g_ad2[NMAX];

// ---------------------------------------------------------------------------
__global__ void zero_k(int n1) {  // zero g_count[0..n1-1]
    int i = blockIdx.x * blockDim.x + threadIdx.x;
    if (i < n1) g_count[i] = 0;
}

__global__ void hist_k(const int* __restrict__ ei, int E, int ET) {
    int i = blockIdx.x * blockDim.x + threadIdx.x;
    if (i >= ET) return;
    int dst = (i < E) ? ei[E + i] : (i - E);
    atomicAdd(&g_count[dst], 1);
}

// single-block exclusive scan over g_count[0..n-1] -> g_off[0..n], g_cursor
__global__ void scan_k(int n) {
    __shared__ int sh[1024];
    int t = threadIdx.x;
    int carry = 0;
    for (int base = 0; base < n; base += 1024) {
        int i = base + t;
        int v = (i < n) ? g_count[i] : 0;
        sh[t] = v;
        __syncthreads();
        int x = v;
        for (int off = 1; off < 1024; off <<= 1) {
            int add = (t >= off) ? sh[t - off] : 0;
            __syncthreads();
            x += add;
            sh[t] = x;
            __syncthreads();
        }
        if (i < n) {
            int ex = carry + x - v;
            g_off[i] = ex;
            g_cursor[i] = ex;
        }
        int tot = sh[1023];
        __syncthreads();
        carry += tot;
    }
    if (t == 0) g_off[n] = carry;
}

__global__ void scatter_k(const int* __restrict__ ei, const float* __restrict__ ew,
                          int E, int ET) {
    int i = blockIdx.x * blockDim.x + threadIdx.x;
    if (i >= ET) return;
    int src, dst; float w;
    if (i < E) { src = ei[i]; dst = ei[E + i]; w = ew[i]; }
    else       { src = i - E; dst = i - E;     w = 1.0f; }
    int pos = atomicAdd(&g_cursor[dst], 1);
    g_srcs[pos] = src;
    g_ews[pos]  = w;
}

// ---------------------------------------------------------------------------
// GEMM1: C[M,256] = A[M,256] @ B[256,256], 64x64 tiles, 4x4 per thread
__global__ void gemm1_k(const float* __restrict__ A, const float* __restrict__ B, int M) {
    __shared__ float As[16][68];
    __shared__ float Bs[16][64];
    int t = threadIdx.x;            // 256 threads
    int tx = t & 15, ty = t >> 4;
    int bm0 = blockIdx.x * 64, bn0 = blockIdx.y * 64;
    int ar = t >> 2, ac = (t & 3) << 2;
    int br = t >> 4, bc = (t & 15) << 2;
    float acc[4][4];
#pragma unroll
    for (int i = 0; i < 4; i++)
#pragma unroll
        for (int j = 0; j < 4; j++) acc[i][j] = 0.f;

    for (int k0 = 0; k0 < 256; k0 += 16) {
        int arow = bm0 + ar;
        float4 av = make_float4(0.f, 0.f, 0.f, 0.f);
        if (arow < M) av = *(const float4*)&A[(size_t)arow * 256 + k0 + ac];
        As[ac + 0][ar] = av.x;
        As[ac + 1][ar] = av.y;
        As[ac + 2][ar] = av.z;
        As[ac + 3][ar] = av.w;
        *(float4*)&Bs[br][bc] = *(const float4*)&B[(size_t)(k0 + br) * 256 + bn0 + bc];
        __syncthreads();
#pragma unroll
        for (int k = 0; k < 16; k++) {
            float4 a = *(const float4*)&As[k][ty << 2];
            float4 b = *(const float4*)&Bs[k][tx << 2];
            float aa[4] = {a.x, a.y, a.z, a.w};
            float bb[4] = {b.x, b.y, b.z, b.w};
#pragma unroll
            for (int i = 0; i < 4; i++)
#pragma unroll
                for (int j = 0; j < 4; j++)
                    acc[i][j] = fmaf(aa[i], bb[j], acc[i][j]);
        }
        __syncthreads();
    }
#pragma unroll
    for (int i = 0; i < 4; i++) {
        int row = bm0 + (ty << 2) + i;
        if (row < M) {
            float4 v = make_float4(acc[i][0], acc[i][1], acc[i][2], acc[i][3]);
            *(float4*)&g_h1[(size_t)row * 256 + bn0 + (tx << 2)] = v;
        }
    }
}

// per-node, per-head attention coefficients a_s1/a_d1 (warp == head)
__global__ void att1_k(const float* __restrict__ attS, const float* __restrict__ attD) {
    int n = blockIdx.x, t = threadIdx.x;
    float v = g_h1[(size_t)n * 256 + t];
    float s = v * attS[t];
    float d = v * attD[t];
#pragma unroll
    for (int off = 16; off > 0; off >>= 1) {
        s += __shfl_xor_sync(0xffffffffu, s, off);
        d += __shfl_xor_sync(0xffffffffu, d, off);
    }
    if ((t & 31) == 0) {
        g_as1[n * 8 + (t >> 5)] = s;
        g_ad1[n * 8 + (t >> 5)] = d;
    }
}

// layer-1 fused softmax + aggregation: block = one dst node, thread = (head,feat)
__global__ void agg1_k(const float* __restrict__ b1) {
    int n = blockIdx.x;
    int t = threadIdx.x;          // 256
    int head = t >> 5;
    __shared__ float w_sh[32][8];
    __shared__ int   s_sh[32];
    int beg = g_off[n], end = g_off[n + 1];
    float acc = 0.f, dn = 0.f;

    for (int base = beg; base < end; base += 32) {
        int cnt = min(32, end - base);
        if (t < cnt) {
            int s = g_srcs[base + t];
            float eww = g_ews[base + t];
            s_sh[t] = s;
            float4 a0 = *(const float4*)&g_as1[s * 8];
            float4 a1 = *(const float4*)&g_as1[s * 8 + 4];
            float4 d0 = *(const float4*)&g_ad1[n * 8];
            float4 d1 = *(const float4*)&g_ad1[n * 8 + 4];
            float as[8] = {a0.x, a0.y, a0.z, a0.w, a1.x, a1.y, a1.z, a1.w};
            float ad[8] = {d0.x, d0.y, d0.z, d0.w, d1.x, d1.y, d1.z, d1.w};
#pragma unroll
            for (int h = 0; h < 8; h++) {
                float lg = as[h] + ad[h];
                lg = lg > 0.f ? lg : 0.2f * lg;
                w_sh[t][h] = __expf(lg * eww);
            }
        }
        __syncthreads();
        for (int jj = 0; jj < cnt; jj++) {
            float wv  = w_sh[jj][head];
            float val = g_h1[(size_t)s_sh[jj] * 256 + t];
            acc = fmaf(wv, val, acc);
            dn += wv;
        }
        __syncthreads();
    }
    float o = acc / (dn + 1e-16f) + b1[t];
    o = o > 0.f ? o : (__expf(o) - 1.f);     // ELU
    g_hE[(size_t)n * 256 + t] = o;
}

// GEMM2 (256->16) + fused a_s2/a_d2; one warp per node, 8 nodes per block
__global__ void gemm2_k(const float* __restrict__ W2, const float* __restrict__ attS,
                        const float* __restrict__ attD, int N) {
    __shared__ float Ws[256 * 17];
    int t = threadIdx.x;
    for (int idx = t; idx < 4096; idx += 256)
        Ws[(idx >> 4) * 17 + (idx & 15)] = W2[idx];
    __syncthreads();
    int lane = t & 31;
    int n = blockIdx.x * 8 + (t >> 5);
    if (n >= N) return;
    const float* row = g_hE + (size_t)n * 256;
    float acc[16];
#pragma unroll
    for (int c = 0; c < 16; c++) acc[c] = 0.f;
    for (int k = lane; k < 256; k += 32) {
        float v = row[k];
        const float* w = &Ws[k * 17];
#pragma unroll
        for (int c = 0; c < 16; c++) acc[c] = fmaf(v, w[c], acc[c]);
    }
#pragma unroll
    for (int off = 16; off > 0; off >>= 1)
#pragma unroll
        for (int c = 0; c < 16; c++)
            acc[c] += __shfl_xor_sync(0xffffffffu, acc[c], off);
    if (lane == 0) {
        float as = 0.f, ad = 0.f;
#pragma unroll
        for (int c = 0; c < 16; c++) {
            g_h2[n * 16 + c] = acc[c];
            as = fmaf(acc[c], attS[c], as);
            ad = fmaf(acc[c], attD[c], ad);
        }
        g_as2[n] = as;
        g_ad2[n] = ad;
    }
}

// layer-2 fused softmax + aggregation: warp per dst node
__global__ void agg2_k(const float* __restrict__ b2, float* __restrict__ out, int N) {
    int lane = threadIdx.x & 31;
    int n = blockIdx.x * 8 + (threadIdx.x >> 5);
    if (n >= N) return;
    int beg = g_off[n], end = g_off[n + 1];
    float ad = g_ad2[n];
    float acc[16];
#pragma unroll
    for (int c = 0; c < 16; c++) acc[c] = 0.f;
    float dn = 0.f;
    for (int j = beg + lane; j < end; j += 32) {
        int s = g_srcs[j];
        float eww = g_ews[j];
        float lg = g_as2[s] + ad;
        lg = lg > 0.f ? lg : 0.2f * lg;
        float wv = __expf(lg * eww);
        dn += wv;
        const float4* hp = (const float4*)&g_h2[s * 16];
        float4 v0 = hp[0], v1 = hp[1], v2 = hp[2], v3 = hp[3];
        acc[0]  = fmaf(wv, v0.x, acc[0]);
        acc[1]  = fmaf(wv, v0.y, acc[1]);
        acc[2]  = fmaf(wv, v0.z, acc[2]);
        acc[3]  = fmaf(wv, v0.w, acc[3]);
        acc[4]  = fmaf(wv, v1.x, acc[4]);
        acc[5]  = fmaf(wv, v1.y, acc[5]);
        acc[6]  = fmaf(wv, v1.z, acc[6]);
        acc[7]  = fmaf(wv, v1.w, acc[7]);
        acc[8]  = fmaf(wv, v2.x, acc[8]);
        acc[9]  = fmaf(wv, v2.y, acc[9]);
        acc[10] = fmaf(wv, v2.z, acc[10]);
        acc[11] = fmaf(wv, v2.w, acc[11]);
        acc[12] = fmaf(wv, v3.x, acc[12]);
        acc[13] = fmaf(wv, v3.y, acc[13]);
        acc[14] = fmaf(wv, v3.z, acc[14]);
        acc[15] = fmaf(wv, v3.w, acc[15]);
    }
#pragma unroll
    for (int off = 16; off > 0; off >>= 1) {
        dn += __shfl_xor_sync(0xffffffffu, dn, off);
#pragma unroll
        for (int c = 0; c < 16; c++)
            acc[c] += __shfl_xor_sync(0xffffffffu, acc[c], off);
    }
    if (lane == 0) {
        float inv = 1.f / (dn + 1e-16f);
#pragma unroll
        for (int c = 0; c < 16; c++)
            out[(size_t)n * 16 + c] = fmaf(acc[c], inv, b2[c]);
    }
}

// ---------------------------------------------------------------------------
extern "C" void kernel_launch(void* const* d_in, const int* in_sizes, int n_in,
                              void* d_out, int out_size) {
    const float* x     = (const float*)d_in[0];
    const int*   ei    = (const int*)  d_in[1];
    const float* ew    = (const float*)d_in[2];
    const float* W1    = (const float*)d_in[3];
    const float* attS1 = (const float*)d_in[4];
    const float* attD1 = (const float*)d_in[5];
    const float* b1    = (const float*)d_in[6];
    const float* W2    = (const float*)d_in[7];
    const float* attS2 = (const float*)d_in[8];
    const float* attD2 = (const float*)d_in[9];
    const float* b2    = (const float*)d_in[10];
    float* out = (float*)d_out;

    int N  = in_sizes[0] / 256;
    int E  = in_sizes[2];
    int ET = E + N;

    // build dst-sorted edge list
    zero_k<<<(N + 1 + 255) / 256, 256>>>(N + 1);
    hist_k<<<(ET + 255) / 256, 256>>>(ei, E, ET);
    scan_k<<<1, 1024>>>(N);
    scatter_k<<<(ET + 255) / 256, 256>>>(ei, ew, E, ET);

    // layer 1
    gemm1_k<<<dim3((N + 63) / 64, 4), 256>>>(x, W1, N);
    att1_k<<<N, 256>>>(attS1, attD1);
    agg1_k<<<N, 256>>>(b1);

    // layer 2
    gemm2_k<<<(N + 7) / 8, 256>>>(W2, attS2, attD2, N);
    agg2_k<<<(N + 7) / 8, 256>>>(b2, out, N);
}

// round 3
// speedup vs baseline: 1.4056x; 1.4056x over previous
#include <cuda_runtime.h>
#include <cuda_bf16.h>
#include <cstdint>

// ---------------------------------------------------------------------------
// GAT 2-layer forward, round 3 (no tcgen05 — harness targets base sm_103):
//   - bucketed counting sort of edges by dst (no scan)
//   - GEMM1 via mma.sync m16n8k16 bf16, 2-term hi/lo split (~fp32 accuracy),
//     a_s1/a_d1 fused into the epilogue (warp N-tile == one head)
//   - agg1: block per dst node, single-pass softmax-weighted sum, ELU
//   - GEMM2 (256->16) + fused a_s2/a_d2; agg2 warp per node
// ---------------------------------------------------------------------------

#define NMAX 20000
#define EMAX 320000
#define CAP  128

__device__ int   g_cnt[NMAX];
__device__ int2  g_edge[NMAX * CAP];
__device__ __nv_bfloat16 g_Bhi[256 * 256];   // W1^T hi split, [N=256][K=256]
__device__ __nv_bfloat16 g_Blo[256 * 256];   // W1^T lo split
__device__ float g_h1[(size_t)NMAX * 256];
__device__ float g_hE[(size_t)NMAX * 256];
__device__ float g_as1[NMAX * 8];
__device__ float g_ad1[NMAX * 8];
__device__ float g_h2[NMAX * 16];
__device__ float g_as2[NMAX];
__device__ float g_ad2[NMAX];

// ------------------------------ helpers ------------------------------------
__device__ __forceinline__ uint32_t smem_u32(const void* p) {
    uint32_t a;
    asm("{ .reg .u64 t; cvta.to.shared.u64 t, %1; cvt.u32.u64 %0, t; }"
        : "=r"(a) : "l"(p));
    return a;
}
__device__ __forceinline__ void ldm_x4(uint32_t& r0, uint32_t& r1,
                                       uint32_t& r2, uint32_t& r3, uint32_t a) {
    asm volatile("ldmatrix.sync.aligned.m8n8.x4.shared.b16 {%0,%1,%2,%3}, [%4];"
                 : "=r"(r0), "=r"(r1), "=r"(r2), "=r"(r3) : "r"(a));
}
__device__ __forceinline__ void ldm_x2(uint32_t& r0, uint32_t& r1, uint32_t a) {
    asm volatile("ldmatrix.sync.aligned.m8n8.x2.shared.b16 {%0,%1}, [%2];"
                 : "=r"(r0), "=r"(r1) : "r"(a));
}
__device__ __forceinline__ void mma16816(float* c, uint32_t a0, uint32_t a1,
                                         uint32_t a2, uint32_t a3,
                                         uint32_t b0, uint32_t b1) {
    asm volatile(
        "mma.sync.aligned.m16n8k16.row.col.f32.bf16.bf16.f32 "
        "{%0,%1,%2,%3},{%4,%5,%6,%7},{%8,%9},{%0,%1,%2,%3};"
        : "+f"(c[0]), "+f"(c[1]), "+f"(c[2]), "+f"(c[3])
        : "r"(a0), "r"(a1), "r"(a2), "r"(a3), "r"(b0), "r"(b1));
}
__device__ __forceinline__ uint32_t pack_bf16(float x, float y) {
    return (uint32_t)__bfloat16_as_ushort(__float2bfloat16(x)) |
           ((uint32_t)__bfloat16_as_ushort(__float2bfloat16(y)) << 16);
}

// ------------------------------ sort (buckets) -----------------------------
__global__ void zero_k(int n) {
    int i = blockIdx.x * blockDim.x + threadIdx.x;
    if (i < n) g_cnt[i] = 0;
}

__global__ void scatter_k(const int* __restrict__ ei, const float* __restrict__ ew,
                          int E, int ET) {
    int i = blockIdx.x * blockDim.x + threadIdx.x;
    if (i >= ET) return;
    int src, dst; float w;
    if (i < E) { src = ei[i]; dst = ei[E + i]; w = ew[i]; }
    else       { src = i - E; dst = i - E;     w = 1.0f; }
    int r = atomicAdd(&g_cnt[dst], 1);
    if (r < CAP) g_edge[dst * CAP + r] = make_int2(src, __float_as_int(w));
}

// ------------------------------ W1 split prep ------------------------------
__global__ void prep_w1_k(const float* __restrict__ W1) {
    int i = blockIdx.x * blockDim.x + threadIdx.x;
    if (i >= 65536) return;
    int k = i >> 8, n = i & 255;          // W1 is [K=256][N=256]
    float v = W1[i];
    __nv_bfloat16 h = __float2bfloat16(v);
    g_Bhi[n * 256 + k] = h;
    g_Blo[n * 256 + k] = __float2bfloat16(v - __bfloat162float(h));
}

// ------------------------------ GEMM1 (HMMA) -------------------------------
// h1[M,256] = x[M,256] @ W1[256,256].  Block tile 128x128, 8 warps,
// warp tile 64x32 (4x4 m16n8k16).  2-term bf16 split: D += Ah*Bh+Ah*Bl+Al*Bh.
// Epilogue: warp N-tile (32 cols) == one head -> a_s1/a_d1 via quad shfl.
#define ASTR 40   // smem row stride in bf16 elems (80B, conflict-free ldmatrix)

__global__ void __launch_bounds__(256)
gemm1_mma(const float* __restrict__ x, const float* __restrict__ attS,
          const float* __restrict__ attD, int M) {
    __shared__ __nv_bfloat16 Ah[128 * ASTR], Al[128 * ASTR];
    __shared__ __nv_bfloat16 Bh[128 * ASTR], Bl[128 * ASTR];

    int tid = threadIdx.x, lane = tid & 31, wid = tid >> 5;
    int warp_m = wid & 1, warp_n = wid >> 1;       // 2 x 4 warp grid
    int row0 = blockIdx.x * 128;
    int col0 = blockIdx.y * 128;

    float acc[4][4][4];                            // [mt][nt][c0..c3]
#pragma unroll
    for (int a = 0; a < 4; a++)
#pragma unroll
        for (int b = 0; b < 4; b++)
#pragma unroll
            for (int c = 0; c < 4; c++) acc[a][b][c] = 0.f;

    // per-thread load coords: row = tid>>1 (0..127), half = (tid&1)*16
    int lrow = tid >> 1, lhalf = (tid & 1) * 16;
    int grow = row0 + lrow;
    bool rv = grow < M;

    // ldmatrix source addresses (fixed per thread, col varies by kk)
    uint32_t a_hi_base = smem_u32(Ah), a_lo_base = smem_u32(Al);
    uint32_t b_hi_base = smem_u32(Bh), b_lo_base = smem_u32(Bl);
    int a_r = warp_m * 64 + (lane & 15);
    int a_c8 = (lane >> 4) * 8;
    int b_r = warp_n * 32 + (lane & 7);
    int b_c8 = ((lane >> 3) & 1) * 8;

    for (int ks = 0; ks < 8; ks++) {
        int k0 = ks * 32;
        __syncthreads();
        // --- stage A (fp32 -> hi/lo bf16) ---
        {
            float4 v[4];
#pragma unroll
            for (int j = 0; j < 4; j++)
                v[j] = rv ? *(const float4*)&x[(size_t)grow * 256 + k0 + lhalf + j * 4]
                          : make_float4(0.f, 0.f, 0.f, 0.f);
#pragma unroll
            for (int j = 0; j < 4; j++) {
                float hx = __bfloat162float(__float2bfloat16(v[j].x));
                float hy = __bfloat162float(__float2bfloat16(v[j].y));
                float hz = __bfloat162float(__float2bfloat16(v[j].z));
                float hw = __bfloat162float(__float2bfloat16(v[j].w));
                uint2 hv = make_uint2(pack_bf16(v[j].x, v[j].y), pack_bf16(v[j].z, v[j].w));
                uint2 lv = make_uint2(pack_bf16(v[j].x - hx, v[j].y - hy),
                                      pack_bf16(v[j].z - hz, v[j].w - hw));
                int e = lrow * ASTR + lhalf + j * 4;
                *(uint2*)&Ah[e] = hv;
                *(uint2*)&Al[e] = lv;
            }
        }
        // --- stage B (copy bf16 splits) ---
        {
            int n = lrow;                          // 0..127 within col block
            const uint4* sh = (const uint4*)&g_Bhi[(col0 + n) * 256 + k0 + lhalf];
            const uint4* sl = (const uint4*)&g_Blo[(col0 + n) * 256 + k0 + lhalf];
            int e = n * ASTR + lhalf;
            *(uint4*)&Bh[e] = sh[0];
            *(uint4*)&Bh[e + 8] = sh[1];
            *(uint4*)&Bl[e] = sl[0];
            *(uint4*)&Bl[e + 8] = sl[1];
        }
        __syncthreads();

#pragma unroll
        for (int kk = 0; kk < 2; kk++) {
            int colk = kk * 16;
            uint32_t ah[4][4], al[4][4], bh[4][2], bl[4][2];
#pragma unroll
            for (int mt = 0; mt < 4; mt++) {
                uint32_t off = (uint32_t)(((a_r + mt * 16) * ASTR + colk + a_c8) * 2);
                ldm_x4(ah[mt][0], ah[mt][1], ah[mt][2], ah[mt][3], a_hi_base + off);
                ldm_x4(al[mt][0], al[mt][1], al[mt][2], al[mt][3], a_lo_base + off);
            }
#pragma unroll
            for (int nt = 0; nt < 4; nt++) {
                uint32_t off = (uint32_t)(((b_r + nt * 8) * ASTR + colk + b_c8) * 2);
                ldm_x2(bh[nt][0], bh[nt][1], b_hi_base + off);
                ldm_x2(bl[nt][0], bl[nt][1], b_lo_base + off);
            }
#pragma unroll
            for (int mt = 0; mt < 4; mt++)
#pragma unroll
                for (int nt = 0; nt < 4; nt++) {
                    mma16816(acc[mt][nt], ah[mt][0], ah[mt][1], ah[mt][2], ah[mt][3],
                             bh[nt][0], bh[nt][1]);
                    mma16816(acc[mt][nt], ah[mt][0], ah[mt][1], ah[mt][2], ah[mt][3],
                             bl[nt][0], bl[nt][1]);
                    mma16816(acc[mt][nt], al[mt][0], al[mt][1], al[mt][2], al[mt][3],
                             bh[nt][0], bh[nt][1]);
                }
        }
    }

    // --- epilogue: store h1 + fused a_s1/a_d1 ---
    int head = (col0 >> 5) + warp_n;               // this warp's 32 cols = one head
    int colw = col0 + warp_n * 32;                 // warp col base (global)
    int quad = lane >> 2, qt = lane & 3;

    // preload att coefficients for this warp's 8 cols (per thread: 2 cols x 4 ntiles)
    float aS[4][2], aD[4][2];
#pragma unroll
    for (int nt = 0; nt < 4; nt++) {
        int c = colw + nt * 8 + qt * 2;
        aS[nt][0] = __ldg(&attS[c]);     aS[nt][1] = __ldg(&attS[c + 1]);
        aD[nt][0] = __ldg(&attD[c]);     aD[nt][1] = __ldg(&attD[c + 1]);
    }
#pragma unroll
    for (int mt = 0; mt < 4; mt++) {
        int r_lo = row0 + warp_m * 64 + mt * 16 + quad;
        int r_hi = r_lo + 8;
        float s_lo = 0.f, d_lo = 0.f, s_hi = 0.f, d_hi = 0.f;
#pragma unroll
        for (int nt = 0; nt < 4; nt++) {
            float c0 = acc[mt][nt][0], c1 = acc[mt][nt][1];
            float c2 = acc[mt][nt][2], c3 = acc[mt][nt][3];
            s_lo = fmaf(c0, aS[nt][0], fmaf(c1, aS[nt][1], s_lo));
            d_lo = fmaf(c0, aD[nt][0], fmaf(c1, aD[nt][1], d_lo));
            s_hi = fmaf(c2, aS[nt][0], fmaf(c3, aS[nt][1], s_hi));
            d_hi = fmaf(c2, aD[nt][0], fmaf(c3, aD[nt][1], d_hi));
            int c = colw + nt * 8 + qt * 2;
            if (r_lo < M) *(float2*)&g_h1[(size_t)r_lo * 256 + c] = make_float2(c0, c1);
            if (r_hi < M) *(float2*)&g_h1[(size_t)r_hi * 256 + c] = make_float2(c2, c3);
        }
#pragma unroll
        for (int off = 2; off > 0; off >>= 1) {
            s_lo += __shfl_xor_sync(0xffffffffu, s_lo, off);
            d_lo += __shfl_xor_sync(0xffffffffu, d_lo, off);
            s_hi += __shfl_xor_sync(0xffffffffu, s_hi, off);
            d_hi += __shfl_xor_sync(0xffffffffu, d_hi, off);
        }
        if (qt == 0) {
            if (r_lo < M) { g_as1[r_lo * 8 + head] = s_lo; g_ad1[r_lo * 8 + head] = d_lo; }
            if (r_hi < M) { g_as1[r_hi * 8 + head] = s_hi; g_ad1[r_hi * 8 + head] = d_hi; }
        }
    }
}

// ------------------------------ agg1 ---------------------------------------
// block = one dst node (256 thr = 8 heads x 32 feat); single-pass softmax
__global__ void agg1_k(const float* __restrict__ b1) {
    int n = blockIdx.x, t = threadIdx.x, head = t >> 5;
    __shared__ float w_sh[32][9];
    __shared__ int   s_sh[32];
    int deg = g_cnt[n];
    const int2* eb = &g_edge[n * CAP];
    float ad[8];
    {
        float4 d0 = *(const float4*)&g_ad1[n * 8];
        float4 d1 = *(const float4*)&g_ad1[n * 8 + 4];
        ad[0]=d0.x; ad[1]=d0.y; ad[2]=d0.z; ad[3]=d0.w;
        ad[4]=d1.x; ad[5]=d1.y; ad[6]=d1.z; ad[7]=d1.w;
    }
    float acc = 0.f, dn = 0.f;
    for (int b0 = 0; b0 < deg; b0 += 32) {
        int cnt = min(32, deg - b0);
        if (t < cnt) {
            int2 e = eb[b0 + t];
            int s = e.x;
            float w = __int_as_float(e.y);
            s_sh[t] = s;
            float4 a0 = *(const float4*)&g_as1[s * 8];
            float4 a1 = *(const float4*)&g_as1[s * 8 + 4];
            float as[8] = {a0.x, a0.y, a0.z, a0.w, a1.x, a1.y, a1.z, a1.w};
#pragma unroll
            for (int h = 0; h < 8; h++) {
                float lg = as[h] + ad[h];
                lg = lg > 0.f ? lg : 0.2f * lg;
                w_sh[t][h] = __expf(lg * w);
            }
        }
        __syncthreads();
        int jj = 0;
        for (; jj + 4 <= cnt; jj += 4) {
            float w0 = w_sh[jj][head],   w1 = w_sh[jj+1][head];
            float w2 = w_sh[jj+2][head], w3 = w_sh[jj+3][head];
            float v0 = __ldg(&g_h1[(size_t)s_sh[jj]   * 256 + t]);
            float v1 = __ldg(&g_h1[(size_t)s_sh[jj+1] * 256 + t]);
            float v2 = __ldg(&g_h1[(size_t)s_sh[jj+2] * 256 + t]);
            float v3 = __ldg(&g_h1[(size_t)s_sh[jj+3] * 256 + t]);
            acc = fmaf(w0, v0, acc); acc = fmaf(w1, v1, acc);
            acc = fmaf(w2, v2, acc); acc = fmaf(w3, v3, acc);
            dn += (w0 + w1) + (w2 + w3);
        }
        for (; jj < cnt; jj++) {
            float wv = w_sh[jj][head];
            acc = fmaf(wv, __ldg(&g_h1[(size_t)s_sh[jj] * 256 + t]), acc);
            dn += wv;
        }
        __syncthreads();
    }
    float o = acc / (dn + 1e-16f) + b1[t];
    o = o > 0.f ? o : (__expf(o) - 1.f);     // ELU
    g_hE[(size_t)n * 256 + t] = o;
}

// ------------------------------ GEMM2 + att2 -------------------------------
__global__ void gemm2_k(const float* __restrict__ W2, const float* __restrict__ attS,
                        const float* __restrict__ attD, int N) {
    __shared__ float Ws[256 * 17];
    int t = threadIdx.x;
    for (int idx = t; idx < 4096; idx += 256)
        Ws[(idx >> 4) * 17 + (idx & 15)] = W2[idx];
    __syncthreads();
    int lane = t & 31;
    int n = blockIdx.x * 8 + (t >> 5);
    if (n >= N) return;
    const float* row = g_hE + (size_t)n * 256;
    float acc[16];
#pragma unroll
    for (int c = 0; c < 16; c++) acc[c] = 0.f;
    for (int k = lane; k < 256; k += 32) {
        float v = row[k];
        const float* w = &Ws[k * 17];
#pragma unroll
        for (int c = 0; c < 16; c++) acc[c] = fmaf(v, w[c], acc[c]);
    }
#pragma unroll
    for (int off = 16; off > 0; off >>= 1)
#pragma unroll
        for (int c = 0; c < 16; c++)
            acc[c] += __shfl_xor_sync(0xffffffffu, acc[c], off);
    if (lane == 0) {
        float as = 0.f, adv = 0.f;
#pragma unroll
        for (int c = 0; c < 16; c++) {
            g_h2[n * 16 + c] = acc[c];
            as  = fmaf(acc[c], attS[c], as);
            adv = fmaf(acc[c], attD[c], adv);
        }
        g_as2[n] = as;
        g_ad2[n] = adv;
    }
}

// ------------------------------ agg2 ---------------------------------------
__global__ void agg2_k(const float* __restrict__ b2, float* __restrict__ out, int N) {
    int lane = threadIdx.x & 31;
    int n = blockIdx.x * 8 + (threadIdx.x >> 5);
    if (n >= N) return;
    int deg = g_cnt[n];
    const int2* eb = &g_edge[n * CAP];
    float adv = g_ad2[n];
    float acc[16];
#pragma unroll
    for (int c = 0; c < 16; c++) acc[c] = 0.f;
    float dn = 0.f;
    for (int j = lane; j < deg; j += 32) {
        int2 e = eb[j];
        int s = e.x;
        float eww = __int_as_float(e.y);
        float lg = g_as2[s] + adv;
        lg = lg > 0.f ? lg : 0.2f * lg;
        float wv = __expf(lg * eww);
        dn += wv;
        const float4* hp = (const float4*)&g_h2[s * 16];
        float4 v0 = hp[0], v1 = hp[1], v2 = hp[2], v3 = hp[3];
        acc[0]  = fmaf(wv, v0.x, acc[0]);  acc[1]  = fmaf(wv, v0.y, acc[1]);
        acc[2]  = fmaf(wv, v0.z, acc[2]);  acc[3]  = fmaf(wv, v0.w, acc[3]);
        acc[4]  = fmaf(wv, v1.x, acc[4]);  acc[5]  = fmaf(wv, v1.y, acc[5]);
        acc[6]  = fmaf(wv, v1.z, acc[6]);  acc[7]  = fmaf(wv, v1.w, acc[7]);
        acc[8]  = fmaf(wv, v2.x, acc[8]);  acc[9]  = fmaf(wv, v2.y, acc[9]);
        acc[10] = fmaf(wv, v2.z, acc[10]); acc[11] = fmaf(wv, v2.w, acc[11]);
        acc[12] = fmaf(wv, v3.x, acc[12]); acc[13] = fmaf(wv, v3.y, acc[13]);
        acc[14] = fmaf(wv, v3.z, acc[14]); acc[15] = fmaf(wv, v3.w, acc[15]);
    }
#pragma unroll
    for (int off = 16; off > 0; off >>= 1) {
        dn += __shfl_xor_sync(0xffffffffu, dn, off);
#pragma unroll
        for (int c = 0; c < 16; c++)
            acc[c] += __shfl_xor_sync(0xffffffffu, acc[c], off);
    }
    if (lane == 0) {
        float inv = 1.f / (dn + 1e-16f);
#pragma unroll
        for (int c = 0; c < 16; c++)
            out[(size_t)n * 16 + c] = fmaf(acc[c], inv, b2[c]);
    }
}

// ---------------------------------------------------------------------------
extern "C" void kernel_launch(void* const* d_in, const int* in_sizes, int n_in,
                              void* d_out, int out_size) {
    const float* x     = (const float*)d_in[0];
    const int*   ei    = (const int*)  d_in[1];
    const float* ew    = (const float*)d_in[2];
    const float* W1    = (const float*)d_in[3];
    const float* attS1 = (const float*)d_in[4];
    const float* attD1 = (const float*)d_in[5];
    const float* b1    = (const float*)d_in[6];
    const float* W2    = (const float*)d_in[7];
    const float* attS2 = (const float*)d_in[8];
    const float* attD2 = (const float*)d_in[9];
    const float* b2    = (const float*)d_in[10];
    float* out = (float*)d_out;

    int N  = in_sizes[0] / 256;
    int E  = in_sizes[2];
    int ET = E + N;

    // bucketed edge sort by dst
    zero_k<<<(N + 255) / 256, 256>>>(N);
    scatter_k<<<(ET + 255) / 256, 256>>>(ei, ew, E, ET);

    // W1 bf16 split (transposed)
    prep_w1_k<<<256, 256>>>(W1);

    // layer 1
    gemm1_mma<<<dim3((N + 127) / 128, 2), 256>>>(x, attS1, attD1, N);
    agg1_k<<<N, 256>>>(b1);

    // layer 2
    gemm2_k<<<(N + 7) / 8, 256>>>(W2, attS2, attD2, N);
    agg2_k<<<(N + 7) / 8, 256>>>(b2, out, N);
}

// round 5
// speedup vs baseline: 1.6532x; 1.1761x over previous
#include <cuda_runtime.h>
#include <cuda_bf16.h>
#include <cuda_fp16.h>
#include <cstdint>

// ---------------------------------------------------------------------------
// GAT 2-layer forward, round 5 (round-4 design + cp.async offset fix):
//   - bucketed counting sort of edges by dst (4 edges/thread for ILP)
//   - GEMM1 via mma.sync m16n8k16 bf16 2-term split, software-pipelined
//     (A prefetched in regs, B via cp.async); h1 stored fp16; att1 fused
//   - agg1: 128 thr/node, half2 gathers, single-pass softmax, ELU -> hE fp32
//   - GEMM2 (256->16) + fused a_s2/a_d2; agg2 warp per node
// ---------------------------------------------------------------------------

#define NMAX 20000
#define EMAX 320000
#define CAP  128

__device__ int   g_cnt[NMAX];
__device__ int2  g_edge[NMAX * CAP];
__device__ __nv_bfloat16 g_Bhi[256 * 256];   // W1^T hi split, [N=256][K=256]
__device__ __nv_bfloat16 g_Blo[256 * 256];   // W1^T lo split
__device__ __half g_h1h[(size_t)NMAX * 256]; // h1 in fp16
__device__ float g_hE[(size_t)NMAX * 256];
__device__ float g_as1[NMAX * 8];
__device__ float g_ad1[NMAX * 8];
__device__ float g_h2[NMAX * 16];
__device__ float g_as2[NMAX];
__device__ float g_ad2[NMAX];

// ------------------------------ helpers ------------------------------------
__device__ __forceinline__ uint32_t smem_u32(const void* p) {
    uint32_t a;
    asm("{ .reg .u64 t; cvta.to.shared.u64 t, %1; cvt.u32.u64 %0, t; }"
        : "=r"(a) : "l"(p));
    return a;
}
__device__ __forceinline__ void ldm_x4(uint32_t& r0, uint32_t& r1,
                                       uint32_t& r2, uint32_t& r3, uint32_t a) {
    asm volatile("ldmatrix.sync.aligned.m8n8.x4.shared.b16 {%0,%1,%2,%3}, [%4];"
                 : "=r"(r0), "=r"(r1), "=r"(r2), "=r"(r3) : "r"(a));
}
__device__ __forceinline__ void ldm_x2(uint32_t& r0, uint32_t& r1, uint32_t a) {
    asm volatile("ldmatrix.sync.aligned.m8n8.x2.shared.b16 {%0,%1}, [%2];"
                 : "=r"(r0), "=r"(r1) : "r"(a));
}
__device__ __forceinline__ void mma16816(float* c, uint32_t a0, uint32_t a1,
                                         uint32_t a2, uint32_t a3,
                                         uint32_t b0, uint32_t b1) {
    asm volatile(
        "mma.sync.aligned.m16n8k16.row.col.f32.bf16.bf16.f32 "
        "{%0,%1,%2,%3},{%4,%5,%6,%7},{%8,%9},{%0,%1,%2,%3};"
        : "+f"(c[0]), "+f"(c[1]), "+f"(c[2]), "+f"(c[3])
        : "r"(a0), "r"(a1), "r"(a2), "r"(a3), "r"(b0), "r"(b1));
}
__device__ __forceinline__ uint32_t pack_bf16(float x, float y) {
    return (uint32_t)__bfloat16_as_ushort(__float2bfloat16(x)) |
           ((uint32_t)__bfloat16_as_ushort(__float2bfloat16(y)) << 16);
}
#define CP16(dst, src) \
    asm volatile("cp.async.cg.shared.global [%0], [%1], 16;" :: "r"(dst), "l"(src))
#define CP_COMMIT() asm volatile("cp.async.commit_group;")
#define CP_WAIT0()  asm volatile("cp.async.wait_group 0;")

// ------------------------------ sort (buckets) -----------------------------
__global__ void zero_k(int n) {
    int i = blockIdx.x * blockDim.x + threadIdx.x;
    if (i < n) g_cnt[i] = 0;
}

__global__ void scatter_k(const int* __restrict__ ei, const float* __restrict__ ew,
                          int E, int ET) {
    int i0 = (blockIdx.x * blockDim.x + threadIdx.x) * 4;
    if (i0 >= ET) return;
    int srcs[4], dsts[4]; float ws[4]; int cnt = 0;
#pragma unroll
    for (int u = 0; u < 4; u++) {
        int i = i0 + u;
        if (i >= ET) break;
        if (i < E) { srcs[u] = ei[i]; dsts[u] = ei[E + i]; ws[u] = ew[i]; }
        else       { srcs[u] = i - E; dsts[u] = i - E;     ws[u] = 1.0f; }
        cnt++;
    }
#pragma unroll
    for (int u = 0; u < 4; u++) {
        if (u >= cnt) break;
        int r = atomicAdd(&g_cnt[dsts[u]], 1);
        if (r < CAP) g_edge[dsts[u] * CAP + r] = make_int2(srcs[u], __float_as_int(ws[u]));
    }
}

// ------------------------------ W1 split prep ------------------------------
__global__ void prep_w1_k(const float* __restrict__ W1) {
    int i = blockIdx.x * blockDim.x + threadIdx.x;
    if (i >= 65536) return;
    int k = i >> 8, n = i & 255;          // W1 is [K=256][N=256]
    float v = W1[i];
    __nv_bfloat16 h = __float2bfloat16(v);
    g_Bhi[n * 256 + k] = h;
    g_Blo[n * 256 + k] = __float2bfloat16(v - __bfloat162float(h));
}

// ------------------------------ GEMM1 (HMMA, pipelined) --------------------
#define ASTR 40   // smem row stride in bf16 elems (80B, conflict-free ldmatrix)

__global__ void __launch_bounds__(256, 2)
gemm1_mma(const float* __restrict__ x, const float* __restrict__ attS,
          const float* __restrict__ attD, int M) {
    __shared__ __nv_bfloat16 Ah[128 * ASTR], Al[128 * ASTR];
    __shared__ __nv_bfloat16 Bh[128 * ASTR], Bl[128 * ASTR];

    int tid = threadIdx.x, lane = tid & 31, wid = tid >> 5;
    int warp_m = wid & 1, warp_n = wid >> 1;       // 2 x 4 warp grid
    int row0 = blockIdx.x * 128;
    int col0 = blockIdx.y * 128;

    float acc[4][4][4];
#pragma unroll
    for (int a = 0; a < 4; a++)
#pragma unroll
        for (int b = 0; b < 4; b++)
#pragma unroll
            for (int c = 0; c < 4; c++) acc[a][b][c] = 0.f;

    int lrow = tid >> 1, lhalf = (tid & 1) * 16;
    int grow = row0 + lrow;
    bool rv = grow < M;

    uint32_t a_hi_base = smem_u32(Ah), a_lo_base = smem_u32(Al);
    uint32_t b_hi_base = smem_u32(Bh), b_lo_base = smem_u32(Bl);
    int a_r = warp_m * 64 + (lane & 15);
    int a_c8 = (lane >> 4) * 8;
    int b_r = warp_n * 32 + (lane & 7);
    int b_c8 = ((lane >> 3) & 1) * 8;

    uint32_t bh_dst = b_hi_base + (uint32_t)((lrow * ASTR + lhalf) * 2);
    uint32_t bl_dst = b_lo_base + (uint32_t)((lrow * ASTR + lhalf) * 2);
    const char* bh_src0 = (const char*)&g_Bhi[(col0 + lrow) * 256 + lhalf];
    const char* bl_src0 = (const char*)&g_Blo[(col0 + lrow) * 256 + lhalf];

    // prefetch A chunk 0
    float4 av[4];
#pragma unroll
    for (int j = 0; j < 4; j++)
        av[j] = rv ? *(const float4*)&x[(size_t)grow * 256 + 0 + lhalf + j * 4]
                   : make_float4(0.f, 0.f, 0.f, 0.f);

    for (int ks = 0; ks < 8; ks++) {
        int k0 = ks * 32;
        __syncthreads();                       // previous chunk consumed
        // B via cp.async: 16 contiguous bf16 = 32B = two 16B copies (+0, +16)
        CP16(bh_dst,      bh_src0 + k0 * 2);
        CP16(bh_dst + 16, bh_src0 + k0 * 2 + 16);
        CP16(bl_dst,      bl_src0 + k0 * 2);
        CP16(bl_dst + 16, bl_src0 + k0 * 2 + 16);
        CP_COMMIT();
        // A: convert prefetched regs -> hi/lo, STS
#pragma unroll
        for (int j = 0; j < 4; j++) {
            float hx = __bfloat162float(__float2bfloat16(av[j].x));
            float hy = __bfloat162float(__float2bfloat16(av[j].y));
            float hz = __bfloat162float(__float2bfloat16(av[j].z));
            float hw = __bfloat162float(__float2bfloat16(av[j].w));
            uint2 hv = make_uint2(pack_bf16(av[j].x, av[j].y), pack_bf16(av[j].z, av[j].w));
            uint2 lv = make_uint2(pack_bf16(av[j].x - hx, av[j].y - hy),
                                  pack_bf16(av[j].z - hz, av[j].w - hw));
            int e = lrow * ASTR + lhalf + j * 4;
            *(uint2*)&Ah[e] = hv;
            *(uint2*)&Al[e] = lv;
        }
        // prefetch next A chunk (latency hidden under MMA below)
        if (ks < 7) {
#pragma unroll
            for (int j = 0; j < 4; j++)
                av[j] = rv ? *(const float4*)&x[(size_t)grow * 256 + k0 + 32 + lhalf + j * 4]
                           : make_float4(0.f, 0.f, 0.f, 0.f);
        }
        CP_WAIT0();
        __syncthreads();

#pragma unroll
        for (int kk = 0; kk < 2; kk++) {
            int colk = kk * 16;
            uint32_t bh[4][2], bl[4][2];
#pragma unroll
            for (int nt = 0; nt < 4; nt++) {
                uint32_t off = (uint32_t)(((b_r + nt * 8) * ASTR + colk + b_c8) * 2);
                ldm_x2(bh[nt][0], bh[nt][1], b_hi_base + off);
                ldm_x2(bl[nt][0], bl[nt][1], b_lo_base + off);
            }
#pragma unroll
            for (int mt = 0; mt < 4; mt++) {
                uint32_t off = (uint32_t)(((a_r + mt * 16) * ASTR + colk + a_c8) * 2);
                uint32_t ah0, ah1, ah2, ah3, al0, al1, al2, al3;
                ldm_x4(ah0, ah1, ah2, ah3, a_hi_base + off);
                ldm_x4(al0, al1, al2, al3, a_lo_base + off);
#pragma unroll
                for (int nt = 0; nt < 4; nt++) {
                    mma16816(acc[mt][nt], ah0, ah1, ah2, ah3, bh[nt][0], bh[nt][1]);
                    mma16816(acc[mt][nt], ah0, ah1, ah2, ah3, bl[nt][0], bl[nt][1]);
                    mma16816(acc[mt][nt], al0, al1, al2, al3, bh[nt][0], bh[nt][1]);
                }
            }
        }
    }

    // --- epilogue: store h1 (fp16) + fused a_s1/a_d1 ---
    int head = (col0 >> 5) + warp_n;
    int colw = col0 + warp_n * 32;
    int quad = lane >> 2, qt = lane & 3;

    float aS[4][2], aD[4][2];
#pragma unroll
    for (int nt = 0; nt < 4; nt++) {
        int c = colw + nt * 8 + qt * 2;
        aS[nt][0] = __ldg(&attS[c]);     aS[nt][1] = __ldg(&attS[c + 1]);
        aD[nt][0] = __ldg(&attD[c]);     aD[nt][1] = __ldg(&attD[c + 1]);
    }
#pragma unroll
    for (int mt = 0; mt < 4; mt++) {
        int r_lo = row0 + warp_m * 64 + mt * 16 + quad;
        int r_hi = r_lo + 8;
        float s_lo = 0.f, d_lo = 0.f, s_hi = 0.f, d_hi = 0.f;
#pragma unroll
        for (int nt = 0; nt < 4; nt++) {
            float c0 = acc[mt][nt][0], c1 = acc[mt][nt][1];
            float c2 = acc[mt][nt][2], c3 = acc[mt][nt][3];
            s_lo = fmaf(c0, aS[nt][0], fmaf(c1, aS[nt][1], s_lo));
            d_lo = fmaf(c0, aD[nt][0], fmaf(c1, aD[nt][1], d_lo));
            s_hi = fmaf(c2, aS[nt][0], fmaf(c3, aS[nt][1], s_hi));
            d_hi = fmaf(c2, aD[nt][0], fmaf(c3, aD[nt][1], d_hi));
            int c = colw + nt * 8 + qt * 2;
            if (r_lo < M) *(__half2*)&g_h1h[(size_t)r_lo * 256 + c] = __floats2half2_rn(c0, c1);
            if (r_hi < M) *(__half2*)&g_h1h[(size_t)r_hi * 256 + c] = __floats2half2_rn(c2, c3);
        }
#pragma unroll
        for (int off = 2; off > 0; off >>= 1) {
            s_lo += __shfl_xor_sync(0xffffffffu, s_lo, off);
            d_lo += __shfl_xor_sync(0xffffffffu, d_lo, off);
            s_hi += __shfl_xor_sync(0xffffffffu, s_hi, off);
            d_hi += __shfl_xor_sync(0xffffffffu, d_hi, off);
        }
        if (qt == 0) {
            if (r_lo < M) { g_as1[r_lo * 8 + head] = s_lo; g_ad1[r_lo * 8 + head] = d_lo; }
            if (r_hi < M) { g_as1[r_hi * 8 + head] = s_hi; g_ad1[r_hi * 8 + head] = d_hi; }
        }
    }
}

// ------------------------------ agg1 ---------------------------------------
// block = one dst node, 128 threads = 8 heads x 16 lanes, half2 feature pairs
__global__ void __launch_bounds__(128)
agg1_k(const float* __restrict__ b1) {
    int n = blockIdx.x, t = threadIdx.x;
    int head = t >> 4;
    int col = head * 32 + (t & 15) * 2;
    __shared__ float w_sh[32][9];
    __shared__ int   s_sh[32];
    __shared__ float ad_sh[8];
    int deg = min(g_cnt[n], CAP);
    const int2* eb = &g_edge[n * CAP];
    if (t < 8) ad_sh[t] = g_ad1[n * 8 + t];
    __syncthreads();

    float ax = 0.f, ay = 0.f, dn = 0.f;
    for (int b0 = 0; b0 < deg; b0 += 32) {
        int cnt = min(32, deg - b0);
        if (t < cnt) {
            int2 e = eb[b0 + t];
            int s = e.x;
            float w = __int_as_float(e.y);
            s_sh[t] = s;
            float4 a0 = *(const float4*)&g_as1[s * 8];
            float4 a1 = *(const float4*)&g_as1[s * 8 + 4];
            float as[8] = {a0.x, a0.y, a0.z, a0.w, a1.x, a1.y, a1.z, a1.w};
#pragma unroll
            for (int h = 0; h < 8; h++) {
                float lg = as[h] + ad_sh[h];
                lg = lg > 0.f ? lg : 0.2f * lg;
                w_sh[t][h] = __expf(lg * w);
            }
        }
        __syncthreads();
        int jj = 0;
        for (; jj + 4 <= cnt; jj += 4) {
            float w0 = w_sh[jj][head],   w1 = w_sh[jj+1][head];
            float w2 = w_sh[jj+2][head], w3 = w_sh[jj+3][head];
            __half2 v0 = *(const __half2*)&g_h1h[(size_t)s_sh[jj]   * 256 + col];
            __half2 v1 = *(const __half2*)&g_h1h[(size_t)s_sh[jj+1] * 256 + col];
            __half2 v2 = *(const __half2*)&g_h1h[(size_t)s_sh[jj+2] * 256 + col];
            __half2 v3 = *(const __half2*)&g_h1h[(size_t)s_sh[jj+3] * 256 + col];
            float2 f0 = __half22float2(v0), f1 = __half22float2(v1);
            float2 f2 = __half22float2(v2), f3 = __half22float2(v3);
            ax = fmaf(w0, f0.x, ax); ay = fmaf(w0, f0.y, ay);
            ax = fmaf(w1, f1.x, ax); ay = fmaf(w1, f1.y, ay);
            ax = fmaf(w2, f2.x, ax); ay = fmaf(w2, f2.y, ay);
            ax = fmaf(w3, f3.x, ax); ay = fmaf(w3, f3.y, ay);
            dn += (w0 + w1) + (w2 + w3);
        }
        for (; jj < cnt; jj++) {
            float wv = w_sh[jj][head];
            float2 f = __half22float2(*(const __half2*)&g_h1h[(size_t)s_sh[jj] * 256 + col]);
            ax = fmaf(wv, f.x, ax); ay = fmaf(wv, f.y, ay);
            dn += wv;
        }
        __syncthreads();
    }
    float inv = 1.f / (dn + 1e-16f);
    float o0 = ax * inv + __ldg(&b1[col]);
    float o1 = ay * inv + __ldg(&b1[col + 1]);
    o0 = o0 > 0.f ? o0 : (__expf(o0) - 1.f);
    o1 = o1 > 0.f ? o1 : (__expf(o1) - 1.f);
    *(float2*)&g_hE[(size_t)n * 256 + col] = make_float2(o0, o1);
}

// ------------------------------ GEMM2 + att2 -------------------------------
__global__ void gemm2_k(const float* __restrict__ W2, const float* __restrict__ attS,
                        const float* __restrict__ attD, int N) {
    __shared__ float Ws[256 * 17];
    int t = threadIdx.x;
    for (int idx = t; idx < 4096; idx += 256)
        Ws[(idx >> 4) * 17 + (idx & 15)] = W2[idx];
    __syncthreads();
    int lane = t & 31;
    int n = blockIdx.x * 8 + (t >> 5);
    if (n >= N) return;
    const float* row = g_hE + (size_t)n * 256;
    float acc[16];
#pragma unroll
    for (int c = 0; c < 16; c++) acc[c] = 0.f;
    for (int k = lane; k < 256; k += 32) {
        float v = row[k];
        const float* w = &Ws[k * 17];
#pragma unroll
        for (int c = 0; c < 16; c++) acc[c] = fmaf(v, w[c], acc[c]);
    }
#pragma unroll
    for (int off = 16; off > 0; off >>= 1)
#pragma unroll
        for (int c = 0; c < 16; c++)
            acc[c] += __shfl_xor_sync(0xffffffffu, acc[c], off);
    if (lane == 0) {
        float as = 0.f, adv = 0.f;
#pragma unroll
        for (int c = 0; c < 16; c++) {
            g_h2[n * 16 + c] = acc[c];
            as  = fmaf(acc[c], attS[c], as);
            adv = fmaf(acc[c], attD[c], adv);
        }
        g_as2[n] = as;
        g_ad2[n] = adv;
    }
}

// ------------------------------ agg2 ---------------------------------------
__global__ void agg2_k(const float* __restrict__ b2, float* __restrict__ out, int N) {
    int lane = threadIdx.x & 31;
    int n = blockIdx.x * 8 + (threadIdx.x >> 5);
    if (n >= N) return;
    int deg = min(g_cnt[n], CAP);
    const int2* eb = &g_edge[n * CAP];
    float adv = g_ad2[n];
    float acc[16];
#pragma unroll
    for (int c = 0; c < 16; c++) acc[c] = 0.f;
    float dn = 0.f;
    for (int j = lane; j < deg; j += 32) {
        int2 e = eb[j];
        int s = e.x;
        float eww = __int_as_float(e.y);
        float lg = g_as2[s] + adv;
        lg = lg > 0.f ? lg : 0.2f * lg;
        float wv = __expf(lg * eww);
        dn += wv;
        const float4* hp = (const float4*)&g_h2[s * 16];
        float4 v0 = hp[0], v1 = hp[1], v2 = hp[2], v3 = hp[3];
        acc[0]  = fmaf(wv, v0.x, acc[0]);  acc[1]  = fmaf(wv, v0.y, acc[1]);
        acc[2]  = fmaf(wv, v0.z, acc[2]);  acc[3]  = fmaf(wv, v0.w, acc[3]);
        acc[4]  = fmaf(wv, v1.x, acc[4]);  acc[5]  = fmaf(wv, v1.y, acc[5]);
        acc[6]  = fmaf(wv, v1.z, acc[6]);  acc[7]  = fmaf(wv, v1.w, acc[7]);
        acc[8]  = fmaf(wv, v2.x, acc[8]);  acc[9]  = fmaf(wv, v2.y, acc[9]);
        acc[10] = fmaf(wv, v2.z, acc[10]); acc[11] = fmaf(wv, v2.w, acc[11]);
        acc[12] = fmaf(wv, v3.x, acc[12]); acc[13] = fmaf(wv, v3.y, acc[13]);
        acc[14] = fmaf(wv, v3.z, acc[14]); acc[15] = fmaf(wv, v3.w, acc[15]);
    }
#pragma unroll
    for (int off = 16; off > 0; off >>= 1) {
        dn += __shfl_xor_sync(0xffffffffu, dn, off);
#pragma unroll
        for (int c = 0; c < 16; c++)
            acc[c] += __shfl_xor_sync(0xffffffffu, acc[c], off);
    }
    if (lane == 0) {
        float inv = 1.f / (dn + 1e-16f);
#pragma unroll
        for (int c = 0; c < 16; c++)
            out[(size_t)n * 16 + c] = fmaf(acc[c], inv, b2[c]);
    }
}

// ---------------------------------------------------------------------------
extern "C" void kernel_launch(void* const* d_in, const int* in_sizes, int n_in,
                              void* d_out, int out_size) {
    const float* x     = (const float*)d_in[0];
    const int*   ei    = (const int*)  d_in[1];
    const float* ew    = (const float*)d_in[2];
    const float* W1    = (const float*)d_in[3];
    const float* attS1 = (const float*)d_in[4];
    const float* attD1 = (const float*)d_in[5];
    const float* b1    = (const float*)d_in[6];
    const float* W2    = (const float*)d_in[7];
    const float* attS2 = (const float*)d_in[8];
    const float* attD2 = (const float*)d_in[9];
    const float* b2    = (const float*)d_in[10];
    float* out = (float*)d_out;

    int N  = in_sizes[0] / 256;
    int E  = in_sizes[2];
    int ET = E + N;

    // bucketed edge sort by dst
    zero_k<<<(N + 255) / 256, 256>>>(N);
    scatter_k<<<(ET / 4 + 256) / 256, 256>>>(ei, ew, E, ET);

    // W1 bf16 split (transposed)
    prep_w1_k<<<256, 256>>>(W1);

    // layer 1
    gemm1_mma<<<dim3((N + 127) / 128, 2), 256>>>(x, attS1, attD1, N);
    agg1_k<<<N, 128>>>(b1);

    // layer 2
    gemm2_k<<<(N + 7) / 8, 256>>>(W2, attS2, attD2, N);
    agg2_k<<<(N + 7) / 8, 256>>>(b2, out, N);
}